// round 2
// baseline (speedup 1.0000x reference)
#include <cuda_runtime.h>
#include <math.h>

#define NQ     6
#define DIM    64
#define CB     64      // channels
#define TT     2048    // time
#define DD     256     // feature dim
#define NC     128     // chunks per batch
#define CHUNKT 16
#define NCP    60      // circuit params per chunk (2 layers x 30)

// scratch: evolved states, (B*NC, 64) complex
__device__ float2 g_evolved[128 * NC * DIM];

// ---------------- quantum helpers (1 warp = 64 amplitudes, 2/lane) ----------------

__device__ __forceinline__ float2 shxor(float2 a, int m) {
    float2 r;
    r.x = __shfl_xor_sync(0xffffffffu, a.x, m);
    r.y = __shfl_xor_sync(0xffffffffu, a.y, m);
    return r;
}

// RX on wire 0: pair (A0, A1) in-thread. RX = [[c, -is], [-is, c]]
__device__ __forceinline__ void rx_pair(float2& a0, float2& a1, float c, float s) {
    float2 n0 = make_float2(c * a0.x + s * a1.y, c * a0.y - s * a1.x);
    float2 n1 = make_float2(c * a1.x + s * a0.y, c * a1.y - s * a0.x);
    a0 = n0; a1 = n1;
}

__device__ __forceinline__ void gate_rx(int w, float c, float s, float2& A0, float2& A1, int lane) {
    if (w == 0) {
        rx_pair(A0, A1, c, s);
    } else {
        int dr = 1 << (5 - w);
        float2 o0 = shxor(A0, dr), o1 = shxor(A1, dr);
        // symmetric: new = c*mine - i*s*other
        A0 = make_float2(c * A0.x + s * o0.y, c * A0.y - s * o0.x);
        A1 = make_float2(c * A1.x + s * o1.y, c * A1.y - s * o1.x);
    }
}

// RY = [[c, -s], [s, c]]
__device__ __forceinline__ void gate_ry(int w, float c, float s, float2& A0, float2& A1, int lane) {
    if (w == 0) {
        float2 n0 = make_float2(c * A0.x - s * A1.x, c * A0.y - s * A1.y);
        float2 n1 = make_float2(s * A0.x + c * A1.x, s * A0.y + c * A1.y);
        A0 = n0; A1 = n1;
    } else {
        int dr = 1 << (5 - w);
        int bit = (lane >> (5 - w)) & 1;
        float sg = bit ? s : -s;
        float2 o0 = shxor(A0, dr), o1 = shxor(A1, dr);
        A0 = make_float2(c * A0.x + sg * o0.x, c * A0.y + sg * o0.y);
        A1 = make_float2(c * A1.x + sg * o1.x, c * A1.y + sg * o1.y);
    }
}

// RZ = diag(e^{-it/2}, e^{+it/2}); bit0: *(c,-s), bit1: *(c,+s)
__device__ __forceinline__ void gate_rz(int w, float c, float s, float2& A0, float2& A1, int lane) {
    if (w == 0) {
        A0 = make_float2(c * A0.x + s * A0.y, c * A0.y - s * A0.x);
        A1 = make_float2(c * A1.x - s * A1.y, c * A1.y + s * A1.x);
    } else {
        int bit = (lane >> (5 - w)) & 1;
        float sg = bit ? s : -s;
        A0 = make_float2(c * A0.x - sg * A0.y, c * A0.y + sg * A0.x);
        A1 = make_float2(c * A1.x - sg * A1.y, c * A1.y + sg * A1.x);
    }
}

// CRX: apply RX on target where control bit == 1
__device__ __forceinline__ void gate_crx(int cw, int tw, float c, float s, float2& A0, float2& A1, int lane) {
    if (tw == 0) {
        // cw >= 1 always in this ansatz when tw == 0
        int cb = (lane >> (5 - cw)) & 1;
        if (cb) rx_pair(A0, A1, c, s);
    } else {
        int dr = 1 << (5 - tw);
        float2 o0 = shxor(A0, dr), o1 = shxor(A1, dr);
        int cb0, cb1;
        if (cw == 0) { cb0 = 0; cb1 = 1; }   // control = wire 0 (bit5 of full index)
        else { cb0 = cb1 = (lane >> (5 - cw)) & 1; }
        if (cb0) A0 = make_float2(c * A0.x + s * o0.y, c * A0.y - s * o0.x);
        if (cb1) A1 = make_float2(c * A1.x + s * o1.y, c * A1.y - s * o1.x);
    }
}

__device__ void run_ansatz(const float* cs, const float* sn, int layers,
                           float2& A0, float2& A1, int lane) {
    int idx = 0;
    for (int L = 0; L < layers; L++) {
        for (int q = 0; q < NQ; q++) {
            gate_rx(q, cs[idx],     sn[idx],     A0, A1, lane);
            gate_ry(q, cs[idx + 1], sn[idx + 1], A0, A1, lane);
            gate_rz(q, cs[idx + 2], sn[idx + 2], A0, A1, lane);
            idx += 3;
        }
        for (int i = 0; i < NQ; i++) { gate_crx(i, (i + 1) % NQ, cs[idx], sn[idx], A0, A1, lane); idx++; }
        for (int i = NQ - 1; i >= 0; i--) { gate_crx(i, (i + 5) % NQ, cs[idx], sn[idx], A0, A1, lane); idx++; }
    }
}

// ---------------- kernel 1: fused per-chunk pipeline ----------------

__global__ __launch_bounds__(256)
void chunk_kernel(const float* __restrict__ x,
                  const float* __restrict__ emb_w, const float* __restrict__ emb_b,
                  const float* __restrict__ att_w1, const float* __restrict__ att_b1,
                  const float* __restrict__ att_w2, const float* __restrict__ att_b2,
                  const float* __restrict__ proj_w, const float* __restrict__ proj_b)
{
    __shared__ float xs[CB][CHUNKT];     // 4KB  raw x slice
    __shared__ float fsm[DD][CHUNKT];    // 16KB feats (d-major, t contiguous)
    __shared__ float red[8][8];          // per-warp score partials
    __shared__ float wgt[CHUNKT];        // scores -> softmax weights
    __shared__ float cvec[DD];           // aggregated chunk vector
    __shared__ float pp[4][NCP];         // proj partials
    __shared__ float prm[NCP];           // sigmoid params (angles)
    __shared__ float pcs[NCP], psn[NCP]; // cos/sin of half-angles

    const int chunk = blockIdx.x;
    const int b  = chunk >> 7;
    const int tc = chunk & (NC - 1);
    const int t0 = tc * CHUNKT;
    const int tid = threadIdx.x;

    // load x slice (64 channels x 16 timesteps)
    for (int i = tid; i < CB * CHUNKT; i += 256) {
        int c = i >> 4, t = i & 15;
        xs[c][t] = x[((size_t)b * CB + c) * TT + t0 + t];
    }
    __syncthreads();

    // feats: thread tid owns feature d = tid for all 16 timesteps
    float facc[16];
    {
        float bias = emb_b[tid];
        #pragma unroll
        for (int t = 0; t < 16; t++) facc[t] = bias;
        #pragma unroll 4
        for (int c = 0; c < CB; c++) {
            float w = emb_w[c * DD + tid];
            const float4* xr = (const float4*)xs[c];   // warp-uniform addr -> broadcast
            #pragma unroll
            for (int t4 = 0; t4 < 4; t4++) {
                float4 v = xr[t4];
                facc[t4 * 4 + 0] = fmaf(v.x, w, facc[t4 * 4 + 0]);
                facc[t4 * 4 + 1] = fmaf(v.y, w, facc[t4 * 4 + 1]);
                facc[t4 * 4 + 2] = fmaf(v.z, w, facc[t4 * 4 + 2]);
                facc[t4 * 4 + 3] = fmaf(v.w, w, facc[t4 * 4 + 3]);
            }
        }
        float4* fr = (float4*)fsm[tid];
        fr[0] = make_float4(facc[0], facc[1], facc[2], facc[3]);
        fr[1] = make_float4(facc[4], facc[5], facc[6], facc[7]);
        fr[2] = make_float4(facc[8], facc[9], facc[10], facc[11]);
        fr[3] = make_float4(facc[12], facc[13], facc[14], facc[15]);
    }
    __syncthreads();

    // h = tanh(feats @ att_w1 + b1); scores = h @ att_w2 + b2 (fused, h never stored)
    // thread: j = tid & 127, t-block = (tid>>7)*8 .. +8
    {
        const int j = tid & 127;
        const int half = tid >> 7;
        float hacc[8];
        float b1 = att_b1[j];
        #pragma unroll
        for (int k = 0; k < 8; k++) hacc[k] = b1;
        const float* w1p = att_w1 + j;
        #pragma unroll 4
        for (int d = 0; d < DD; d++) {
            float w = w1p[d * 128];
            const float4* fr = (const float4*)(&fsm[d][half * 8]);  // warp-uniform -> broadcast
            float4 v0 = fr[0], v1 = fr[1];
            hacc[0] = fmaf(v0.x, w, hacc[0]); hacc[1] = fmaf(v0.y, w, hacc[1]);
            hacc[2] = fmaf(v0.z, w, hacc[2]); hacc[3] = fmaf(v0.w, w, hacc[3]);
            hacc[4] = fmaf(v1.x, w, hacc[4]); hacc[5] = fmaf(v1.y, w, hacc[5]);
            hacc[6] = fmaf(v1.z, w, hacc[6]); hacc[7] = fmaf(v1.w, w, hacc[7]);
        }
        float w2 = att_w2[j];
        #pragma unroll
        for (int k = 0; k < 8; k++) {
            float s = tanhf(hacc[k]) * w2;
            #pragma unroll
            for (int off = 16; off; off >>= 1) s += __shfl_xor_sync(0xffffffffu, s, off);
            hacc[k] = s;
        }
        if ((tid & 31) == 0) {
            int wd = tid >> 5;
            #pragma unroll
            for (int k = 0; k < 8; k++) red[wd][k] = hacc[k];
        }
    }
    __syncthreads();

    if (tid < 16) {
        int half = tid >> 3, k = tid & 7;
        float s = att_b2[0]
                + red[half * 4 + 0][k] + red[half * 4 + 1][k]
                + red[half * 4 + 2][k] + red[half * 4 + 3][k];
        wgt[tid] = s;   // scores (temporarily)
    }
    __syncthreads();

    if (tid == 0) {
        float mx = wgt[0];
        #pragma unroll
        for (int t = 1; t < 16; t++) mx = fmaxf(mx, wgt[t]);
        float e[16], ssum = 0.f;
        #pragma unroll
        for (int t = 0; t < 16; t++) { e[t] = expf(wgt[t] - mx); ssum += e[t]; }
        float inv = 1.0f / ssum;
        #pragma unroll
        for (int t = 0; t < 16; t++) wgt[t] = e[t] * inv;
    }
    __syncthreads();

    // aggregate: cvec[d] = sum_t w[t] * feats[t][d]  (feats still live in regs)
    {
        float a = 0.f;
        #pragma unroll
        for (int t = 0; t < 16; t++) a = fmaf(wgt[t], facc[t], a);
        cvec[tid] = a;
    }
    __syncthreads();

    // proj: params = sigmoid(cvec @ proj_w + proj_b), 60 outputs, 4-way split over d
    if (tid < 240) {
        int p = tid % 60, q = tid / 60;
        float a = 0.f;
        #pragma unroll 4
        for (int d = q * 64; d < q * 64 + 64; d++) a = fmaf(cvec[d], proj_w[d * NCP + p], a);
        pp[q][p] = a;
    }
    __syncthreads();
    if (tid < NCP) {
        float a = proj_b[tid] + pp[0][tid] + pp[1][tid] + pp[2][tid] + pp[3][tid];
        prm[tid] = 1.0f / (1.0f + expf(-a));
    }
    __syncthreads();

    // quantum ansatz, warp 0 only
    if (tid < 32) {
        for (int i = tid; i < NCP; i += 32) {
            float sv, cv;
            sincosf(0.5f * prm[i], &sv, &cv);
            pcs[i] = cv; psn[i] = sv;
        }
        __syncwarp();
        float2 A0 = make_float2(0.f, 0.f), A1 = make_float2(0.f, 0.f);
        if (tid == 0) A0.x = 1.0f;
        run_ansatz(pcs, psn, 2, A0, A1, tid);
        g_evolved[(size_t)chunk * DIM + tid]      = A0;
        g_evolved[(size_t)chunk * DIM + 32 + tid] = A1;
    }
}

// ---------------- kernel 2: per-batch mix + QFF + measurement + head ----------------

__device__ __forceinline__ float blk_reduce64(float v, float* r, int tid) {
    __syncthreads();           // protect previous use of r
    r[tid] = v;
    __syncthreads();
    if (tid < 32) {
        float a = r[tid] + r[tid + 32];
        #pragma unroll
        for (int off = 16; off; off >>= 1) a += __shfl_xor_sync(0xffffffffu, a, off);
        if (tid == 0) r[0] = a;
    }
    __syncthreads();
    return r[0];
}

__global__ __launch_bounds__(64)
void batch_kernel(const float* __restrict__ mix_re, const float* __restrict__ mix_im,
                  const float* __restrict__ qff,
                  const float* __restrict__ out_w, const float* __restrict__ out_b,
                  const float* __restrict__ ln_g, const float* __restrict__ ln_b,
                  const float* __restrict__ cls_w1, const float* __restrict__ cls_b1,
                  const float* __restrict__ cls_w2, const float* __restrict__ cls_b2,
                  float* __restrict__ out)
{
    __shared__ float redsm[64];
    __shared__ float2 msm[64];
    __shared__ float qfeat[18];
    __shared__ float osm[256], o2[256], h2sm[256];
    __shared__ float pcs[30], psn[30];

    const int b = blockIdx.x;
    const int tid = threadIdx.x;

    // |coeff| normalization
    float p;
    {
        float r1 = mix_re[tid],      i1 = mix_im[tid];
        float r2 = mix_re[tid + 64], i2 = mix_im[tid + 64];
        p = sqrtf(r1 * r1 + i1 * i1) + sqrtf(r2 * r2 + i2 * i2);
    }
    float S = blk_reduce64(p, redsm, tid);
    float invS = 1.0f / (S + 1e-8f);

    // mixed[i] = sum_t evolved[b,t,i] * coeff[t]
    float2 acc = make_float2(0.f, 0.f);
    const float2* ev = g_evolved + (size_t)b * NC * DIM;
    for (int t = 0; t < NC; t++) {
        float cr = mix_re[t] * invS, ci = mix_im[t] * invS;
        float2 e = ev[t * DIM + tid];
        acc.x += e.x * cr - e.y * ci;
        acc.y += e.x * ci + e.y * cr;
    }
    float nrm2 = blk_reduce64(acc.x * acc.x + acc.y * acc.y, redsm, tid);
    float scale = 1.0f / (sqrtf(nrm2) + 1e-9f);
    msm[tid] = make_float2(acc.x * scale, acc.y * scale);

    if (tid < 30) {
        float sv, cv;
        sincosf(0.5f * qff[tid], &sv, &cv);
        pcs[tid] = cv; psn[tid] = sv;
    }
    __syncthreads();

    if (tid < 32) {
        float2 A0 = msm[tid], A1 = msm[tid + 32];
        run_ansatz(pcs, psn, 1, A0, A1, tid);

        // Z expectations
        float p0 = A0.x * A0.x + A0.y * A0.y;
        float p1 = A1.x * A1.x + A1.y * A1.y;
        for (int w = 0; w < NQ; w++) {
            float zv;
            if (w == 0) zv = p0 - p1;
            else {
                int bit = (tid >> (5 - w)) & 1;
                zv = bit ? -(p0 + p1) : (p0 + p1);
            }
            #pragma unroll
            for (int off = 16; off; off >>= 1) zv += __shfl_xor_sync(0xffffffffu, zv, off);
            if (tid == 0) qfeat[12 + w] = zv;
        }
        // X, Y expectations: 2*Re / 2*Im of sum_pairs conj(a0)*a1
        for (int w = 0; w < NQ; w++) {
            float xr, xi;
            if (w == 0) {
                xr = A0.x * A1.x + A0.y * A1.y;
                xi = A0.x * A1.y - A0.y * A1.x;
            } else {
                int dr = 1 << (5 - w);
                float2 o0 = shxor(A0, dr), o1 = shxor(A1, dr);
                int bit = (tid >> (5 - w)) & 1;
                if (!bit) {
                    xr = A0.x * o0.x + A0.y * o0.y + A1.x * o1.x + A1.y * o1.y;
                    xi = A0.x * o0.y - A0.y * o0.x + A1.x * o1.y - A1.y * o1.x;
                } else { xr = 0.f; xi = 0.f; }
            }
            #pragma unroll
            for (int off = 16; off; off >>= 1) {
                xr += __shfl_xor_sync(0xffffffffu, xr, off);
                xi += __shfl_xor_sync(0xffffffffu, xi, off);
            }
            if (tid == 0) { qfeat[w] = 2.f * xr; qfeat[6 + w] = 2.f * xi; }
        }
    }
    __syncthreads();

    // out = qfeat @ out_w + out_b
    for (int d = tid; d < 256; d += 64) {
        float a = out_b[d];
        #pragma unroll
        for (int k = 0; k < 18; k++) a = fmaf(qfeat[k], out_w[k * 256 + d], a);
        osm[d] = a;
    }
    __syncthreads();

    // LayerNorm
    float ls = 0.f, lq = 0.f;
    for (int d = tid; d < 256; d += 64) { float v = osm[d]; ls += v; lq += v * v; }
    float mean = blk_reduce64(ls, redsm, tid) * (1.0f / 256.0f);
    float e2   = blk_reduce64(lq, redsm, tid) * (1.0f / 256.0f);
    float istd = rsqrtf(e2 - mean * mean + 1e-5f);
    for (int d = tid; d < 256; d += 64)
        o2[d] = (osm[d] - mean) * istd * ln_g[d] + ln_b[d];
    __syncthreads();

    // classifier layer 1
    for (int j = tid; j < 256; j += 64) {
        float a = cls_b1[j];
        #pragma unroll 4
        for (int d = 0; d < 256; d++) a = fmaf(o2[d], cls_w1[d * 256 + j], a);
        h2sm[j] = fmaxf(a, 0.f);
    }
    __syncthreads();

    // classifier layer 2 (2 logits)
    float l0 = 0.f, l1 = 0.f;
    for (int j = tid; j < 256; j += 64) {
        float h = h2sm[j];
        l0 = fmaf(h, cls_w2[j * 2 + 0], l0);
        l1 = fmaf(h, cls_w2[j * 2 + 1], l1);
    }
    l0 = blk_reduce64(l0, redsm, tid);
    l1 = blk_reduce64(l1, redsm, tid);
    if (tid == 0) {
        out[b * 2 + 0] = l0 + cls_b2[0];
        out[b * 2 + 1] = l1 + cls_b2[1];
    }
}

// ---------------- launch ----------------

extern "C" void kernel_launch(void* const* d_in, const int* in_sizes, int n_in,
                              void* d_out, int out_size) {
    const float* x       = (const float*)d_in[0];
    const float* emb_w   = (const float*)d_in[1];
    const float* emb_b   = (const float*)d_in[2];
    const float* att_w1  = (const float*)d_in[3];
    const float* att_b1  = (const float*)d_in[4];
    const float* att_w2  = (const float*)d_in[5];
    const float* att_b2  = (const float*)d_in[6];
    const float* proj_w  = (const float*)d_in[7];
    const float* proj_b  = (const float*)d_in[8];
    const float* mix_re  = (const float*)d_in[9];
    const float* mix_im  = (const float*)d_in[10];
    const float* qff     = (const float*)d_in[11];
    const float* out_w   = (const float*)d_in[12];
    const float* out_b   = (const float*)d_in[13];
    const float* ln_g    = (const float*)d_in[14];
    const float* ln_b    = (const float*)d_in[15];
    const float* cls_w1  = (const float*)d_in[16];
    const float* cls_b1  = (const float*)d_in[17];
    const float* cls_w2  = (const float*)d_in[18];
    const float* cls_b2  = (const float*)d_in[19];

    int B = in_sizes[0] / (CB * TT);

    chunk_kernel<<<B * NC, 256>>>(x, emb_w, emb_b, att_w1, att_b1, att_w2, att_b2,
                                  proj_w, proj_b);
    batch_kernel<<<B, 64>>>(mix_re, mix_im, qff, out_w, out_b, ln_g, ln_b,
                            cls_w1, cls_b1, cls_w2, cls_b2, (float*)d_out);
}

// round 3
// speedup vs baseline: 1.1114x; 1.1114x over previous
#include <cuda_runtime.h>
#include <math.h>

#define NQ     6
#define DIM    64
#define CB     64      // channels
#define TT     2048    // time
#define DD     256     // feature dim
#define NC     128     // chunks per batch
#define CHUNKT 16
#define NCP    60      // circuit params per chunk (2 layers x 30)

typedef unsigned long long u64;

// scratch: evolved states, (B*NC, 64) complex
__device__ float2 g_evolved[128 * NC * DIM];

// ---------------- packed f32x2 helpers ----------------

__device__ __forceinline__ u64 ffma2(u64 a, u64 b, u64 c) {
    u64 d;
    asm("fma.rn.f32x2 %0, %1, %2, %3;" : "=l"(d) : "l"(a), "l"(b), "l"(c));
    return d;
}
__device__ __forceinline__ u64 pack2(float x, float y) {
    u64 r;
    asm("mov.b64 %0, {%1, %2};" : "=l"(r) : "f"(x), "f"(y));
    return r;
}
__device__ __forceinline__ float2 unpack2(u64 v) {
    float2 r;
    asm("mov.b64 {%0, %1}, %2;" : "=f"(r.x), "=f"(r.y) : "l"(v));
    return r;
}

// ---------------- quantum helpers (1 warp = 64 amplitudes, 2/lane) ----------------

__device__ __forceinline__ float2 shxor(float2 a, int m) {
    float2 r;
    r.x = __shfl_xor_sync(0xffffffffu, a.x, m);
    r.y = __shfl_xor_sync(0xffffffffu, a.y, m);
    return r;
}

__device__ __forceinline__ void rx_pair(float2& a0, float2& a1, float c, float s) {
    float2 n0 = make_float2(c * a0.x + s * a1.y, c * a0.y - s * a1.x);
    float2 n1 = make_float2(c * a1.x + s * a0.y, c * a1.y - s * a0.x);
    a0 = n0; a1 = n1;
}

__device__ __forceinline__ void gate_rx(int w, float c, float s, float2& A0, float2& A1, int lane) {
    if (w == 0) {
        rx_pair(A0, A1, c, s);
    } else {
        int dr = 1 << (5 - w);
        float2 o0 = shxor(A0, dr), o1 = shxor(A1, dr);
        A0 = make_float2(c * A0.x + s * o0.y, c * A0.y - s * o0.x);
        A1 = make_float2(c * A1.x + s * o1.y, c * A1.y - s * o1.x);
    }
}

__device__ __forceinline__ void gate_ry(int w, float c, float s, float2& A0, float2& A1, int lane) {
    if (w == 0) {
        float2 n0 = make_float2(c * A0.x - s * A1.x, c * A0.y - s * A1.y);
        float2 n1 = make_float2(s * A0.x + c * A1.x, s * A0.y + c * A1.y);
        A0 = n0; A1 = n1;
    } else {
        int dr = 1 << (5 - w);
        int bit = (lane >> (5 - w)) & 1;
        float sg = bit ? s : -s;
        float2 o0 = shxor(A0, dr), o1 = shxor(A1, dr);
        A0 = make_float2(c * A0.x + sg * o0.x, c * A0.y + sg * o0.y);
        A1 = make_float2(c * A1.x + sg * o1.x, c * A1.y + sg * o1.y);
    }
}

__device__ __forceinline__ void gate_rz(int w, float c, float s, float2& A0, float2& A1, int lane) {
    if (w == 0) {
        A0 = make_float2(c * A0.x + s * A0.y, c * A0.y - s * A0.x);
        A1 = make_float2(c * A1.x - s * A1.y, c * A1.y + s * A1.x);
    } else {
        int bit = (lane >> (5 - w)) & 1;
        float sg = bit ? s : -s;
        A0 = make_float2(c * A0.x - sg * A0.y, c * A0.y + sg * A0.x);
        A1 = make_float2(c * A1.x - sg * A1.y, c * A1.y + sg * A1.x);
    }
}

__device__ __forceinline__ void gate_crx(int cw, int tw, float c, float s, float2& A0, float2& A1, int lane) {
    if (tw == 0) {
        int cb = (lane >> (5 - cw)) & 1;
        if (cb) rx_pair(A0, A1, c, s);
    } else {
        int dr = 1 << (5 - tw);
        float2 o0 = shxor(A0, dr), o1 = shxor(A1, dr);
        int cb0, cb1;
        if (cw == 0) { cb0 = 0; cb1 = 1; }
        else { cb0 = cb1 = (lane >> (5 - cw)) & 1; }
        if (cb0) A0 = make_float2(c * A0.x + s * o0.y, c * A0.y - s * o0.x);
        if (cb1) A1 = make_float2(c * A1.x + s * o1.y, c * A1.y - s * o1.x);
    }
}

__device__ void run_ansatz(const float* cs, const float* sn, int layers,
                           float2& A0, float2& A1, int lane) {
    int idx = 0;
    for (int L = 0; L < layers; L++) {
        for (int q = 0; q < NQ; q++) {
            gate_rx(q, cs[idx],     sn[idx],     A0, A1, lane);
            gate_ry(q, cs[idx + 1], sn[idx + 1], A0, A1, lane);
            gate_rz(q, cs[idx + 2], sn[idx + 2], A0, A1, lane);
            idx += 3;
        }
        for (int i = 0; i < NQ; i++) { gate_crx(i, (i + 1) % NQ, cs[idx], sn[idx], A0, A1, lane); idx++; }
        for (int i = NQ - 1; i >= 0; i--) { gate_crx(i, (i + 5) % NQ, cs[idx], sn[idx], A0, A1, lane); idx++; }
    }
}

// ---------------- kernel 1: fused per-chunk pipeline ----------------

__global__ __launch_bounds__(256)
void chunk_kernel(const float* __restrict__ x,
                  const float* __restrict__ emb_w, const float* __restrict__ emb_b,
                  const float* __restrict__ att_w1, const float* __restrict__ att_b1,
                  const float* __restrict__ att_w2, const float* __restrict__ att_b2,
                  const float* __restrict__ proj_w, const float* __restrict__ proj_b)
{
    __shared__ float xs[CB][CHUNKT];     // 4KB  raw x slice
    __shared__ float fsm[DD][CHUNKT];    // 16KB feats (d-major, t contiguous)
    __shared__ float red[8][8];          // per-warp score partials
    __shared__ float wgt[CHUNKT];        // scores -> softmax weights
    __shared__ float cvec[DD];           // aggregated chunk vector
    __shared__ float pp[4][NCP];         // proj partials
    __shared__ float prm[NCP];           // sigmoid params (angles)
    __shared__ float pcs[NCP], psn[NCP]; // cos/sin of half-angles

    const int chunk = blockIdx.x;
    const int b  = chunk >> 7;
    const int tc = chunk & (NC - 1);
    const int t0 = tc * CHUNKT;
    const int tid = threadIdx.x;

    // load x slice (64 channels x 16 timesteps)
    for (int i = tid; i < CB * CHUNKT; i += 256) {
        int c = i >> 4, t = i & 15;
        xs[c][t] = x[((size_t)b * CB + c) * TT + t0 + t];
    }
    __syncthreads();

    // feats: thread tid owns feature d = tid for all 16 timesteps (packed f32x2)
    u64 facc2[8];
    {
        float bias = emb_b[tid];
        u64 bb = pack2(bias, bias);
        #pragma unroll
        for (int k = 0; k < 8; k++) facc2[k] = bb;
        #pragma unroll 4
        for (int c = 0; c < CB; c++) {
            float w = emb_w[c * DD + tid];
            u64 ww = pack2(w, w);
            const u64* xr = (const u64*)xs[c];   // warp-uniform addr -> broadcast LDS
            #pragma unroll
            for (int k = 0; k < 8; k++) facc2[k] = ffma2(xr[k], ww, facc2[k]);
        }
        u64* fr = (u64*)fsm[tid];
        #pragma unroll
        for (int k = 0; k < 8; k++) fr[k] = facc2[k];
    }
    __syncthreads();

    // h = tanh(feats @ att_w1 + b1); scores = h @ att_w2 + b2 (fused, packed f32x2)
    // thread: j = tid & 127, t-block = (tid>>7)*8 .. +8
    {
        const int j = tid & 127;
        const int half = tid >> 7;
        u64 hacc2[4];
        float b1 = att_b1[j];
        u64 bb = pack2(b1, b1);
        #pragma unroll
        for (int k = 0; k < 4; k++) hacc2[k] = bb;
        const float* w1p = att_w1 + j;
        #pragma unroll 4
        for (int d = 0; d < DD; d++) {
            float w = w1p[d * 128];
            u64 ww = pack2(w, w);
            const u64* fr = (const u64*)(&fsm[d][half * 8]);  // warp-uniform -> broadcast
            hacc2[0] = ffma2(fr[0], ww, hacc2[0]);
            hacc2[1] = ffma2(fr[1], ww, hacc2[1]);
            hacc2[2] = ffma2(fr[2], ww, hacc2[2]);
            hacc2[3] = ffma2(fr[3], ww, hacc2[3]);
        }
        float w2 = att_w2[j];
        float hsc[8];
        #pragma unroll
        for (int k = 0; k < 4; k++) {
            float2 hv = unpack2(hacc2[k]);
            hsc[2 * k]     = tanhf(hv.x) * w2;
            hsc[2 * k + 1] = tanhf(hv.y) * w2;
        }
        #pragma unroll
        for (int k = 0; k < 8; k++) {
            float s = hsc[k];
            #pragma unroll
            for (int off = 16; off; off >>= 1) s += __shfl_xor_sync(0xffffffffu, s, off);
            hsc[k] = s;
        }
        if ((tid & 31) == 0) {
            int wd = tid >> 5;
            #pragma unroll
            for (int k = 0; k < 8; k++) red[wd][k] = hsc[k];
        }
    }
    __syncthreads();

    if (tid < 16) {
        int half = tid >> 3, k = tid & 7;
        float s = att_b2[0]
                + red[half * 4 + 0][k] + red[half * 4 + 1][k]
                + red[half * 4 + 2][k] + red[half * 4 + 3][k];
        wgt[tid] = s;   // scores (temporarily)
    }
    __syncthreads();

    if (tid == 0) {
        float mx = wgt[0];
        #pragma unroll
        for (int t = 1; t < 16; t++) mx = fmaxf(mx, wgt[t]);
        float e[16], ssum = 0.f;
        #pragma unroll
        for (int t = 0; t < 16; t++) { e[t] = expf(wgt[t] - mx); ssum += e[t]; }
        float inv = 1.0f / ssum;
        #pragma unroll
        for (int t = 0; t < 16; t++) wgt[t] = e[t] * inv;
    }
    __syncthreads();

    // aggregate: cvec[d] = sum_t w[t] * feats[t][d]  (feats still live packed in regs)
    {
        u64 a2 = pack2(0.f, 0.f);
        const u64* wp = (const u64*)wgt;
        #pragma unroll
        for (int k = 0; k < 8; k++) a2 = ffma2(facc2[k], wp[k], a2);
        float2 av = unpack2(a2);
        cvec[tid] = av.x + av.y;
    }
    __syncthreads();

    // proj: params = sigmoid(cvec @ proj_w + proj_b), 60 outputs, 4-way split over d
    if (tid < 240) {
        int p = tid % 60, q = tid / 60;
        float a = 0.f;
        #pragma unroll 4
        for (int d = q * 64; d < q * 64 + 64; d++) a = fmaf(cvec[d], proj_w[d * NCP + p], a);
        pp[q][p] = a;
    }
    __syncthreads();
    if (tid < NCP) {
        float a = proj_b[tid] + pp[0][tid] + pp[1][tid] + pp[2][tid] + pp[3][tid];
        prm[tid] = 1.0f / (1.0f + expf(-a));
    }
    __syncthreads();

    // quantum ansatz, warp 0 only
    if (tid < 32) {
        for (int i = tid; i < NCP; i += 32) {
            float sv, cv;
            sincosf(0.5f * prm[i], &sv, &cv);
            pcs[i] = cv; psn[i] = sv;
        }
        __syncwarp();
        float2 A0 = make_float2(0.f, 0.f), A1 = make_float2(0.f, 0.f);
        if (tid == 0) A0.x = 1.0f;
        run_ansatz(pcs, psn, 2, A0, A1, tid);
        g_evolved[(size_t)chunk * DIM + tid]      = A0;
        g_evolved[(size_t)chunk * DIM + 32 + tid] = A1;
    }
}

// ---------------- kernel 2: per-batch mix + QFF + measurement + head ----------------

__device__ __forceinline__ float blk_reduce256(float v, float* r, int tid) {
    __syncthreads();           // protect previous use of r
    r[tid] = v;
    __syncthreads();
    if (tid < 32) {
        float a = r[tid] + r[tid + 32] + r[tid + 64] + r[tid + 96]
                + r[tid + 128] + r[tid + 160] + r[tid + 192] + r[tid + 224];
        #pragma unroll
        for (int off = 16; off; off >>= 1) a += __shfl_xor_sync(0xffffffffu, a, off);
        if (tid == 0) r[0] = a;
    }
    __syncthreads();
    return r[0];
}

__global__ __launch_bounds__(256)
void batch_kernel(const float* __restrict__ mix_re, const float* __restrict__ mix_im,
                  const float* __restrict__ qff,
                  const float* __restrict__ out_w, const float* __restrict__ out_b,
                  const float* __restrict__ ln_g, const float* __restrict__ ln_b,
                  const float* __restrict__ cls_w1, const float* __restrict__ cls_b1,
                  const float* __restrict__ cls_w2, const float* __restrict__ cls_b2,
                  float* __restrict__ out)
{
    __shared__ float redsm[256];
    __shared__ float2 part[4][64];
    __shared__ float2 msm[64];
    __shared__ float qfeat[18];
    __shared__ float o2[256], h2sm[256];
    __shared__ float pcs[30], psn[30];

    const int b = blockIdx.x;
    const int tid = threadIdx.x;

    // |coeff| normalization
    float p = 0.f;
    if (tid < NC) {
        float r1 = mix_re[tid], i1 = mix_im[tid];
        p = sqrtf(r1 * r1 + i1 * i1);
    }
    float S = blk_reduce256(p, redsm, tid);
    float invS = 1.0f / (S + 1e-8f);

    // mixed[i] = sum_t evolved[b,t,i] * coeff[t]; 4-way split over t
    const int amp = tid & 63;
    const int grp = tid >> 6;
    float2 acc = make_float2(0.f, 0.f);
    const float2* ev = g_evolved + (size_t)b * NC * DIM;
    for (int t = grp * 32; t < grp * 32 + 32; t++) {
        float cr = mix_re[t] * invS, ci = mix_im[t] * invS;
        float2 e = ev[t * DIM + amp];
        acc.x += e.x * cr - e.y * ci;
        acc.y += e.x * ci + e.y * cr;
    }
    part[grp][amp] = acc;
    __syncthreads();

    float n2p = 0.f;
    if (tid < 64) {
        float2 m = part[0][tid];
        m.x += part[1][tid].x + part[2][tid].x + part[3][tid].x;
        m.y += part[1][tid].y + part[2][tid].y + part[3][tid].y;
        msm[tid] = m;
        n2p = m.x * m.x + m.y * m.y;
    }
    float nrm2 = blk_reduce256(n2p, redsm, tid);
    float scale = 1.0f / (sqrtf(nrm2) + 1e-9f);
    if (tid < 64) {
        msm[tid].x *= scale;
        msm[tid].y *= scale;
    }
    if (tid >= 64 && tid < 94) {
        int i = tid - 64;
        float sv, cv;
        sincosf(0.5f * qff[i], &sv, &cv);
        pcs[i] = cv; psn[i] = sv;
    }
    __syncthreads();

    if (tid < 32) {
        float2 A0 = msm[tid], A1 = msm[tid + 32];
        run_ansatz(pcs, psn, 1, A0, A1, tid);

        // Z expectations
        float p0 = A0.x * A0.x + A0.y * A0.y;
        float p1 = A1.x * A1.x + A1.y * A1.y;
        for (int w = 0; w < NQ; w++) {
            float zv;
            if (w == 0) zv = p0 - p1;
            else {
                int bit = (tid >> (5 - w)) & 1;
                zv = bit ? -(p0 + p1) : (p0 + p1);
            }
            #pragma unroll
            for (int off = 16; off; off >>= 1) zv += __shfl_xor_sync(0xffffffffu, zv, off);
            if (tid == 0) qfeat[12 + w] = zv;
        }
        // X, Y expectations
        for (int w = 0; w < NQ; w++) {
            float xr, xi;
            if (w == 0) {
                xr = A0.x * A1.x + A0.y * A1.y;
                xi = A0.x * A1.y - A0.y * A1.x;
            } else {
                int dr = 1 << (5 - w);
                float2 o0 = shxor(A0, dr), o1 = shxor(A1, dr);
                int bit = (tid >> (5 - w)) & 1;
                if (!bit) {
                    xr = A0.x * o0.x + A0.y * o0.y + A1.x * o1.x + A1.y * o1.y;
                    xi = A0.x * o0.y - A0.y * o0.x + A1.x * o1.y - A1.y * o1.x;
                } else { xr = 0.f; xi = 0.f; }
            }
            #pragma unroll
            for (int off = 16; off; off >>= 1) {
                xr += __shfl_xor_sync(0xffffffffu, xr, off);
                xi += __shfl_xor_sync(0xffffffffu, xi, off);
            }
            if (tid == 0) { qfeat[w] = 2.f * xr; qfeat[6 + w] = 2.f * xi; }
        }
    }
    __syncthreads();

    // out = qfeat @ out_w + out_b  (one feature per thread)
    float oval = out_b[tid];
    #pragma unroll
    for (int k = 0; k < 18; k++) oval = fmaf(qfeat[k], out_w[k * 256 + tid], oval);

    // LayerNorm
    float mean = blk_reduce256(oval, redsm, tid) * (1.0f / 256.0f);
    float e2   = blk_reduce256(oval * oval, redsm, tid) * (1.0f / 256.0f);
    float istd = rsqrtf(e2 - mean * mean + 1e-5f);
    o2[tid] = (oval - mean) * istd * ln_g[tid] + ln_b[tid];
    __syncthreads();

    // classifier layer 1 (one output per thread, 4 accumulators for ILP)
    {
        float a0 = cls_b1[tid], a1 = 0.f, a2 = 0.f, a3 = 0.f;
        const float* wp = cls_w1 + tid;
        #pragma unroll 4
        for (int d = 0; d < 256; d += 4) {
            a0 = fmaf(o2[d],     wp[d * 256],         a0);
            a1 = fmaf(o2[d + 1], wp[(d + 1) * 256],   a1);
            a2 = fmaf(o2[d + 2], wp[(d + 2) * 256],   a2);
            a3 = fmaf(o2[d + 3], wp[(d + 3) * 256],   a3);
        }
        h2sm[tid] = fmaxf(a0 + a1 + a2 + a3, 0.f);
    }
    __syncthreads();

    // classifier layer 2 (2 logits)
    float h = h2sm[tid];
    float l0 = h * cls_w2[tid * 2 + 0];
    float l1 = h * cls_w2[tid * 2 + 1];
    l0 = blk_reduce256(l0, redsm, tid);
    l1 = blk_reduce256(l1, redsm, tid);
    if (tid == 0) {
        out[b * 2 + 0] = l0 + cls_b2[0];
        out[b * 2 + 1] = l1 + cls_b2[1];
    }
}

// ---------------- launch ----------------

extern "C" void kernel_launch(void* const* d_in, const int* in_sizes, int n_in,
                              void* d_out, int out_size) {
    const float* x       = (const float*)d_in[0];
    const float* emb_w   = (const float*)d_in[1];
    const float* emb_b   = (const float*)d_in[2];
    const float* att_w1  = (const float*)d_in[3];
    const float* att_b1  = (const float*)d_in[4];
    const float* att_w2  = (const float*)d_in[5];
    const float* att_b2  = (const float*)d_in[6];
    const float* proj_w  = (const float*)d_in[7];
    const float* proj_b  = (const float*)d_in[8];
    const float* mix_re  = (const float*)d_in[9];
    const float* mix_im  = (const float*)d_in[10];
    const float* qff     = (const float*)d_in[11];
    const float* out_w   = (const float*)d_in[12];
    const float* out_b   = (const float*)d_in[13];
    const float* ln_g    = (const float*)d_in[14];
    const float* ln_b    = (const float*)d_in[15];
    const float* cls_w1  = (const float*)d_in[16];
    const float* cls_b1  = (const float*)d_in[17];
    const float* cls_w2  = (const float*)d_in[18];
    const float* cls_b2  = (const float*)d_in[19];

    int B = in_sizes[0] / (CB * TT);

    chunk_kernel<<<B * NC, 256>>>(x, emb_w, emb_b, att_w1, att_b1, att_w2, att_b2,
                                  proj_w, proj_b);
    batch_kernel<<<B, 256>>>(mix_re, mix_im, qff, out_w, out_b, ln_g, ln_b,
                             cls_w1, cls_b1, cls_w2, cls_b2, (float*)d_out);
}

// round 5
// speedup vs baseline: 1.1807x; 1.0624x over previous
#include <cuda_runtime.h>
#include <math.h>

#define NQ     6
#define DIM    64
#define CB     64      // channels
#define TT     2048    // time
#define DD     256     // feature dim
#define NC     128     // chunks per batch
#define CHUNKT 16
#define NCP    60      // circuit params per chunk (2 layers x 30)

typedef unsigned long long u64;

// scratch: evolved states, (B*NC, 64) complex
__device__ float2 g_evolved[128 * NC * DIM];

// ---------------- packed f32x2 helpers ----------------

__device__ __forceinline__ u64 ffma2(u64 a, u64 b, u64 c) {
    u64 d;
    asm("fma.rn.f32x2 %0, %1, %2, %3;" : "=l"(d) : "l"(a), "l"(b), "l"(c));
    return d;
}
__device__ __forceinline__ u64 pack2(float x, float y) {
    u64 r;
    asm("mov.b64 %0, {%1, %2};" : "=l"(r) : "f"(x), "f"(y));
    return r;
}
__device__ __forceinline__ float2 unpack2(u64 v) {
    float2 r;
    asm("mov.b64 {%0, %1}, %2;" : "=f"(r.x), "=f"(r.y) : "l"(v));
    return r;
}

// ---------------- quantum helpers (1 warp = 64 amplitudes, 2/lane) ----------------

__device__ __forceinline__ float2 shxor(float2 a, int m) {
    float2 r;
    r.x = __shfl_xor_sync(0xffffffffu, a.x, m);
    r.y = __shfl_xor_sync(0xffffffffu, a.y, m);
    return r;
}

__device__ __forceinline__ void rx_pair(float2& a0, float2& a1, float c, float s) {
    float2 n0 = make_float2(c * a0.x + s * a1.y, c * a0.y - s * a1.x);
    float2 n1 = make_float2(c * a1.x + s * a0.y, c * a1.y - s * a0.x);
    a0 = n0; a1 = n1;
}

__device__ __forceinline__ void gate_rx(int w, float c, float s, float2& A0, float2& A1, int lane) {
    if (w == 0) {
        rx_pair(A0, A1, c, s);
    } else {
        int dr = 1 << (5 - w);
        float2 o0 = shxor(A0, dr), o1 = shxor(A1, dr);
        A0 = make_float2(c * A0.x + s * o0.y, c * A0.y - s * o0.x);
        A1 = make_float2(c * A1.x + s * o1.y, c * A1.y - s * o1.x);
    }
}

__device__ __forceinline__ void gate_ry(int w, float c, float s, float2& A0, float2& A1, int lane) {
    if (w == 0) {
        float2 n0 = make_float2(c * A0.x - s * A1.x, c * A0.y - s * A1.y);
        float2 n1 = make_float2(s * A0.x + c * A1.x, s * A0.y + c * A1.y);
        A0 = n0; A1 = n1;
    } else {
        int dr = 1 << (5 - w);
        int bit = (lane >> (5 - w)) & 1;
        float sg = bit ? s : -s;
        float2 o0 = shxor(A0, dr), o1 = shxor(A1, dr);
        A0 = make_float2(c * A0.x + sg * o0.x, c * A0.y + sg * o0.y);
        A1 = make_float2(c * A1.x + sg * o1.x, c * A1.y + sg * o1.y);
    }
}

__device__ __forceinline__ void gate_rz(int w, float c, float s, float2& A0, float2& A1, int lane) {
    if (w == 0) {
        A0 = make_float2(c * A0.x + s * A0.y, c * A0.y - s * A0.x);
        A1 = make_float2(c * A1.x - s * A1.y, c * A1.y + s * A1.x);
    } else {
        int bit = (lane >> (5 - w)) & 1;
        float sg = bit ? s : -s;
        A0 = make_float2(c * A0.x - sg * A0.y, c * A0.y + sg * A0.x);
        A1 = make_float2(c * A1.x - sg * A1.y, c * A1.y + sg * A1.x);
    }
}

__device__ __forceinline__ void gate_crx(int cw, int tw, float c, float s, float2& A0, float2& A1, int lane) {
    if (tw == 0) {
        int cb = (lane >> (5 - cw)) & 1;
        if (cb) rx_pair(A0, A1, c, s);
    } else {
        int dr = 1 << (5 - tw);
        float2 o0 = shxor(A0, dr), o1 = shxor(A1, dr);
        int cb0, cb1;
        if (cw == 0) { cb0 = 0; cb1 = 1; }
        else { cb0 = cb1 = (lane >> (5 - cw)) & 1; }
        if (cb0) A0 = make_float2(c * A0.x + s * o0.y, c * A0.y - s * o0.x);
        if (cb1) A1 = make_float2(c * A1.x + s * o1.y, c * A1.y - s * o1.x);
    }
}

__device__ void run_ansatz(const float* cs, const float* sn, int layers,
                           float2& A0, float2& A1, int lane) {
    int idx = 0;
    for (int L = 0; L < layers; L++) {
        for (int q = 0; q < NQ; q++) {
            gate_rx(q, cs[idx],     sn[idx],     A0, A1, lane);
            gate_ry(q, cs[idx + 1], sn[idx + 1], A0, A1, lane);
            gate_rz(q, cs[idx + 2], sn[idx + 2], A0, A1, lane);
            idx += 3;
        }
        for (int i = 0; i < NQ; i++) { gate_crx(i, (i + 1) % NQ, cs[idx], sn[idx], A0, A1, lane); idx++; }
        for (int i = NQ - 1; i >= 0; i--) { gate_crx(i, (i + 5) % NQ, cs[idx], sn[idx], A0, A1, lane); idx++; }
    }
}

// ---------------- kernel 1: fused per-chunk pipeline ----------------

__global__ __launch_bounds__(256)
void chunk_kernel(const float* __restrict__ x,
                  const float* __restrict__ emb_w, const float* __restrict__ emb_b,
                  const float* __restrict__ att_w1, const float* __restrict__ att_b1,
                  const float* __restrict__ att_w2, const float* __restrict__ att_b2,
                  const float* __restrict__ proj_w, const float* __restrict__ proj_b)
{
    __shared__ float xs[CB][CHUNKT];          // 4KB  raw x slice
    __shared__ u64 fsm4[DD * 9];              // 18KB feats as t-pairs, row stride 9 u64
    __shared__ float red[8][16];              // per-warp score partials
    __shared__ __align__(16) float wgt[16];   // scores -> softmax weights
    __shared__ float cvec[DD];                // aggregated chunk vector
    __shared__ float pp[4][NCP];              // proj partials
    __shared__ float prm[NCP];                // sigmoid params (angles)
    __shared__ float pcs[NCP], psn[NCP];      // cos/sin of half-angles

    const int chunk = blockIdx.x;
    const int b  = chunk >> 7;
    const int tc = chunk & (NC - 1);
    const int t0c = tc * CHUNKT;
    const int tid = threadIdx.x;

    // load x slice (64 channels x 16 timesteps)
    for (int i = tid; i < CB * CHUNKT; i += 256) {
        int c = i >> 4, t = i & 15;
        xs[c][t] = x[((size_t)b * CB + c) * TT + t0c + t];
    }
    __syncthreads();

    // ---- GEMM 1: feats[d][t] = emb_b[d] + sum_c x[c][t] * emb_w[c][d]
    // thread tile: 4 d x 4 t.  u = d-group (d = 4u..4u+3), tg = t-group (t = 4tg..4tg+3)
    {
        const int u  = tid & 63;
        const int tg = tid >> 6;
        u64 acc00, acc01, acc10, acc11, acc20, acc21, acc30, acc31;
        {
            float4 bv = *(const float4*)(emb_b + 4 * u);
            acc00 = acc01 = pack2(bv.x, bv.x);
            acc10 = acc11 = pack2(bv.y, bv.y);
            acc20 = acc21 = pack2(bv.z, bv.z);
            acc30 = acc31 = pack2(bv.w, bv.w);
        }
        const float* wbase = emb_w + 4 * u;
        #pragma unroll 4
        for (int c = 0; c < CB; c++) {
            float4 xv = *(const float4*)(&xs[c][tg * 4]);   // warp-uniform broadcast
            float4 wv = *(const float4*)(wbase + c * DD);   // coalesced
            u64 xt01 = pack2(xv.x, xv.y);
            u64 xt23 = pack2(xv.z, xv.w);
            u64 w0 = pack2(wv.x, wv.x);
            u64 w1 = pack2(wv.y, wv.y);
            u64 w2 = pack2(wv.z, wv.z);
            u64 w3 = pack2(wv.w, wv.w);
            acc00 = ffma2(xt01, w0, acc00); acc01 = ffma2(xt23, w0, acc01);
            acc10 = ffma2(xt01, w1, acc10); acc11 = ffma2(xt23, w1, acc11);
            acc20 = ffma2(xt01, w2, acc20); acc21 = ffma2(xt23, w2, acc21);
            acc30 = ffma2(xt01, w3, acc30); acc31 = ffma2(xt23, w3, acc31);
        }
        // store t-pairs: fsm4[d*9 + tp], tp = t/2
        int tp = 2 * tg;
        fsm4[(4 * u + 0) * 9 + tp] = acc00; fsm4[(4 * u + 0) * 9 + tp + 1] = acc01;
        fsm4[(4 * u + 1) * 9 + tp] = acc10; fsm4[(4 * u + 1) * 9 + tp + 1] = acc11;
        fsm4[(4 * u + 2) * 9 + tp] = acc20; fsm4[(4 * u + 2) * 9 + tp + 1] = acc31 * 0 + acc21;
        fsm4[(4 * u + 3) * 9 + tp] = acc30; fsm4[(4 * u + 3) * 9 + tp + 1] = acc31;
    }
    __syncthreads();

    // ---- GEMM 2: h[t][j] = tanh(sum_d f[d][t] w1[d][j] + b1[j]); score[t] = sum_j h*w2[j]
    // warp wp: j in [16*wp, 16*wp+16), lane = (jg 0..3) x (th 0..7); thread: 4 j x t-pair th
    {
        const int lane = tid & 31;
        const int wp   = tid >> 5;
        const int jg   = lane & 3;
        const int th   = lane >> 2;
        const int j0   = wp * 16 + jg * 4;
        u64 a00, a01, a10, a11;   // [t][jpair]
        {
            float4 bv = *(const float4*)(att_b1 + j0);
            a00 = a10 = pack2(bv.x, bv.y);
            a01 = a11 = pack2(bv.z, bv.w);
        }
        const float* w1base = att_w1 + j0;
        const u64* fbase = fsm4 + th;
        #pragma unroll 4
        for (int d = 0; d < DD; d++) {
            u64 fv = fbase[d * 9];                           // 8-addr multicast LDS.64
            float4 wv = *(const float4*)(w1base + d * 128);  // 64B per warp
            float2 f = unpack2(fv);
            u64 f0 = pack2(f.x, f.x);
            u64 f1 = pack2(f.y, f.y);
            u64 wj01 = pack2(wv.x, wv.y);
            u64 wj23 = pack2(wv.z, wv.w);
            a00 = ffma2(wj01, f0, a00); a01 = ffma2(wj23, f0, a01);
            a10 = ffma2(wj01, f1, a10); a11 = ffma2(wj23, f1, a11);
        }
        float4 w2v = *(const float4*)(att_w2 + j0);
        float2 p00 = unpack2(a00), p01 = unpack2(a01);
        float2 p10 = unpack2(a10), p11 = unpack2(a11);
        float s0 = tanhf(p00.x) * w2v.x + tanhf(p00.y) * w2v.y
                 + tanhf(p01.x) * w2v.z + tanhf(p01.y) * w2v.w;
        float s1 = tanhf(p10.x) * w2v.x + tanhf(p10.y) * w2v.y
                 + tanhf(p11.x) * w2v.z + tanhf(p11.y) * w2v.w;
        s0 += __shfl_xor_sync(0xffffffffu, s0, 1);
        s0 += __shfl_xor_sync(0xffffffffu, s0, 2);
        s1 += __shfl_xor_sync(0xffffffffu, s1, 1);
        s1 += __shfl_xor_sync(0xffffffffu, s1, 2);
        if (jg == 0) {
            red[wp][2 * th]     = s0;
            red[wp][2 * th + 1] = s1;
        }
    }
    __syncthreads();

    if (tid < 16) {
        float s = att_b2[0];
        #pragma unroll
        for (int w = 0; w < 8; w++) s += red[w][tid];
        wgt[tid] = s;   // scores (temporarily)
    }
    __syncthreads();

    if (tid == 0) {
        float mx = wgt[0];
        #pragma unroll
        for (int t = 1; t < 16; t++) mx = fmaxf(mx, wgt[t]);
        float e[16], ssum = 0.f;
        #pragma unroll
        for (int t = 0; t < 16; t++) { e[t] = expf(wgt[t] - mx); ssum += e[t]; }
        float inv = 1.0f / ssum;
        #pragma unroll
        for (int t = 0; t < 16; t++) wgt[t] = e[t] * inv;
    }
    __syncthreads();

    // aggregate: cvec[d] = sum_t wgt[t] * f[d][t]  (d = tid)
    {
        u64 a2 = pack2(0.f, 0.f);
        const u64* wp2 = (const u64*)wgt;
        const u64* fr = fsm4 + tid * 9;
        #pragma unroll
        for (int k = 0; k < 8; k++) a2 = ffma2(fr[k], wp2[k], a2);
        float2 av = unpack2(a2);
        cvec[tid] = av.x + av.y;
    }
    __syncthreads();

    // proj: params = sigmoid(cvec @ proj_w + proj_b), 60 outputs, 4-way split over d
    if (tid < 240) {
        int p = tid % 60, q = tid / 60;
        float a = 0.f;
        #pragma unroll 4
        for (int d = q * 64; d < q * 64 + 64; d++) a = fmaf(cvec[d], proj_w[d * NCP + p], a);
        pp[q][p] = a;
    }
    __syncthreads();
    if (tid < NCP) {
        float a = proj_b[tid] + pp[0][tid] + pp[1][tid] + pp[2][tid] + pp[3][tid];
        prm[tid] = 1.0f / (1.0f + expf(-a));
    }
    __syncthreads();

    // quantum ansatz, warp 0 only
    if (tid < 32) {
        for (int i = tid; i < NCP; i += 32) {
            float sv, cv;
            sincosf(0.5f * prm[i], &sv, &cv);
            pcs[i] = cv; psn[i] = sv;
        }
        __syncwarp();
        float2 A0 = make_float2(0.f, 0.f), A1 = make_float2(0.f, 0.f);
        if (tid == 0) A0.x = 1.0f;
        run_ansatz(pcs, psn, 2, A0, A1, tid);
        g_evolved[(size_t)chunk * DIM + tid]      = A0;
        g_evolved[(size_t)chunk * DIM + 32 + tid] = A1;
    }
}

// ---------------- kernel 2: per-batch mix + QFF + measurement + head ----------------

__device__ __forceinline__ float blk_reduce256(float v, float* r, int tid) {
    __syncthreads();           // protect previous use of r
    r[tid] = v;
    __syncthreads();
    if (tid < 32) {
        float a = r[tid] + r[tid + 32] + r[tid + 64] + r[tid + 96]
                + r[tid + 128] + r[tid + 160] + r[tid + 192] + r[tid + 224];
        #pragma unroll
        for (int off = 16; off; off >>= 1) a += __shfl_xor_sync(0xffffffffu, a, off);
        if (tid == 0) r[0] = a;
    }
    __syncthreads();
    return r[0];
}

__global__ __launch_bounds__(256)
void batch_kernel(const float* __restrict__ mix_re, const float* __restrict__ mix_im,
                  const float* __restrict__ qff,
                  const float* __restrict__ out_w, const float* __restrict__ out_b,
                  const float* __restrict__ ln_g, const float* __restrict__ ln_b,
                  const float* __restrict__ cls_w1, const float* __restrict__ cls_b1,
                  const float* __restrict__ cls_w2, const float* __restrict__ cls_b2,
                  float* __restrict__ out)
{
    __shared__ float redsm[256];
    __shared__ float2 part[4][64];
    __shared__ float2 msm[64];
    __shared__ float qfeat[18];
    __shared__ float o2[256], h2sm[256];
    __shared__ float pcs[30], psn[30];

    const int b = blockIdx.x;
    const int tid = threadIdx.x;

    // |coeff| normalization
    float p = 0.f;
    if (tid < NC) {
        float r1 = mix_re[tid], i1 = mix_im[tid];
        p = sqrtf(r1 * r1 + i1 * i1);
    }
    float S = blk_reduce256(p, redsm, tid);
    float invS = 1.0f / (S + 1e-8f);

    // mixed[i] = sum_t evolved[b,t,i] * coeff[t]; 4-way split over t
    const int amp = tid & 63;
    const int grp = tid >> 6;
    float2 acc = make_float2(0.f, 0.f);
    const float2* ev = g_evolved + (size_t)b * NC * DIM;
    for (int t = grp * 32; t < grp * 32 + 32; t++) {
        float cr = mix_re[t] * invS, ci = mix_im[t] * invS;
        float2 e = ev[t * DIM + amp];
        acc.x += e.x * cr - e.y * ci;
        acc.y += e.x * ci + e.y * cr;
    }
    part[grp][amp] = acc;
    __syncthreads();

    float n2p = 0.f;
    if (tid < 64) {
        float2 m = part[0][tid];
        m.x += part[1][tid].x + part[2][tid].x + part[3][tid].x;
        m.y += part[1][tid].y + part[2][tid].y + part[3][tid].y;
        msm[tid] = m;
        n2p = m.x * m.x + m.y * m.y;
    }
    float nrm2 = blk_reduce256(n2p, redsm, tid);
    float scale = 1.0f / (sqrtf(nrm2) + 1e-9f);
    if (tid < 64) {
        msm[tid].x *= scale;
        msm[tid].y *= scale;
    }
    if (tid >= 64 && tid < 94) {
        int i = tid - 64;
        float sv, cv;
        sincosf(0.5f * qff[i], &sv, &cv);
        pcs[i] = cv; psn[i] = sv;
    }
    __syncthreads();

    if (tid < 32) {
        float2 A0 = msm[tid], A1 = msm[tid + 32];
        run_ansatz(pcs, psn, 1, A0, A1, tid);

        // Z expectations
        float p0 = A0.x * A0.x + A0.y * A0.y;
        float p1 = A1.x * A1.x + A1.y * A1.y;
        for (int w = 0; w < NQ; w++) {
            float zv;
            if (w == 0) zv = p0 - p1;
            else {
                int bit = (tid >> (5 - w)) & 1;
                zv = bit ? -(p0 + p1) : (p0 + p1);
            }
            #pragma unroll
            for (int off = 16; off; off >>= 1) zv += __shfl_xor_sync(0xffffffffu, zv, off);
            if (tid == 0) qfeat[12 + w] = zv;
        }
        // X, Y expectations
        for (int w = 0; w < NQ; w++) {
            float xr, xi;
            if (w == 0) {
                xr = A0.x * A1.x + A0.y * A1.y;
                xi = A0.x * A1.y - A0.y * A1.x;
            } else {
                int dr = 1 << (5 - w);
                float2 o0 = shxor(A0, dr), o1 = shxor(A1, dr);
                int bit = (tid >> (5 - w)) & 1;
                if (!bit) {
                    xr = A0.x * o0.x + A0.y * o0.y + A1.x * o1.x + A1.y * o1.y;
                    xi = A0.x * o0.y - A0.y * o0.x + A1.x * o1.y - A1.y * o1.x;
                } else { xr = 0.f; xi = 0.f; }
            }
            #pragma unroll
            for (int off = 16; off; off >>= 1) {
                xr += __shfl_xor_sync(0xffffffffu, xr, off);
                xi += __shfl_xor_sync(0xffffffffu, xi, off);
            }
            if (tid == 0) { qfeat[w] = 2.f * xr; qfeat[6 + w] = 2.f * xi; }
        }
    }
    __syncthreads();

    // out = qfeat @ out_w + out_b  (one feature per thread)
    float oval = out_b[tid];
    #pragma unroll
    for (int k = 0; k < 18; k++) oval = fmaf(qfeat[k], out_w[k * 256 + tid], oval);

    // LayerNorm
    float mean = blk_reduce256(oval, redsm, tid) * (1.0f / 256.0f);
    float e2   = blk_reduce256(oval * oval, redsm, tid) * (1.0f / 256.0f);
    float istd = rsqrtf(e2 - mean * mean + 1e-5f);
    o2[tid] = (oval - mean) * istd * ln_g[tid] + ln_b[tid];
    __syncthreads();

    // classifier layer 1 (one output per thread, 4 accumulators for ILP)
    {
        float a0 = cls_b1[tid], a1 = 0.f, a2 = 0.f, a3 = 0.f;
        const float* wp = cls_w1 + tid;
        #pragma unroll 4
        for (int d = 0; d < 256; d += 4) {
            a0 = fmaf(o2[d],     wp[d * 256],         a0);
            a1 = fmaf(o2[d + 1], wp[(d + 1) * 256],   a1);
            a2 = fmaf(o2[d + 2], wp[(d + 2) * 256],   a2);
            a3 = fmaf(o2[d + 3], wp[(d + 3) * 256],   a3);
        }
        h2sm[tid] = fmaxf(a0 + a1 + a2 + a3, 0.f);
    }
    __syncthreads();

    // classifier layer 2 (2 logits)
    float h = h2sm[tid];
    float l0 = h * cls_w2[tid * 2 + 0];
    float l1 = h * cls_w2[tid * 2 + 1];
    l0 = blk_reduce256(l0, redsm, tid);
    l1 = blk_reduce256(l1, redsm, tid);
    if (tid == 0) {
        out[b * 2 + 0] = l0 + cls_b2[0];
        out[b * 2 + 1] = l1 + cls_b2[1];
    }
}

// ---------------- launch ----------------

extern "C" void kernel_launch(void* const* d_in, const int* in_sizes, int n_in,
                              void* d_out, int out_size) {
    const float* x       = (const float*)d_in[0];
    const float* emb_w   = (const float*)d_in[1];
    const float* emb_b   = (const float*)d_in[2];
    const float* att_w1  = (const float*)d_in[3];
    const float* att_b1  = (const float*)d_in[4];
    const float* att_w2  = (const float*)d_in[5];
    const float* att_b2  = (const float*)d_in[6];
    const float* proj_w  = (const float*)d_in[7];
    const float* proj_b  = (const float*)d_in[8];
    const float* mix_re  = (const float*)d_in[9];
    const float* mix_im  = (const float*)d_in[10];
    const float* qff     = (const float*)d_in[11];
    const float* out_w   = (const float*)d_in[12];
    const float* out_b   = (const float*)d_in[13];
    const float* ln_g    = (const float*)d_in[14];
    const float* ln_b    = (const float*)d_in[15];
    const float* cls_w1  = (const float*)d_in[16];
    const float* cls_b1  = (const float*)d_in[17];
    const float* cls_w2  = (const float*)d_in[18];
    const float* cls_b2  = (const float*)d_in[19];

    int B = in_sizes[0] / (CB * TT);

    chunk_kernel<<<B * NC, 256>>>(x, emb_w, emb_b, att_w1, att_b1, att_w2, att_b2,
                                  proj_w, proj_b);
    batch_kernel<<<B, 256>>>(mix_re, mix_im, qff, out_w, out_b, ln_g, ln_b,
                             cls_w1, cls_b1, cls_w2, cls_b2, (float*)d_out);
}